// round 15
// baseline (speedup 1.0000x reference)
#include <cuda_runtime.h>
#include <cuda_bf16.h>

// Problem constants (from reference: N=100000, E=1600000, D=64)
#define MAX_N 100000
#define D 64
#define CAP 64   // per-node edge-list capacity; deg ~ Poisson(16), P(>64) ~ 1e-20
#define BM 64

// Scratch (__device__ globals; no allocs allowed).
// g_cnt relies on static zero-init at module load + self-cleaning in the
// fused kernel: every launch reads then resets each counter, so it is 0 at
// the start of every launch.
__device__ int g_slot[MAX_N * CAP];                     // 25.6 MB
__device__ int g_cnt[MAX_N];                            // 400 KB

// ---------------------------------------------------------------------------
// K1: build per-dst edge lists. 4 edges per thread (int4 loads -> 4
// independent atomic->store chains, 4x MLP on the latency-bound path).
// edge_index is int32: [0..E) = src, [E..2E) = dst.
// ---------------------------------------------------------------------------
__global__ void build_kernel_v4(const int* __restrict__ ei, int E4, int E) {
    int i = blockIdx.x * blockDim.x + threadIdx.x;
    if (i >= E4) return;
    int4 s = __ldg(reinterpret_cast<const int4*>(ei) + i);
    int4 d = __ldg(reinterpret_cast<const int4*>(ei + E) + i);
    int p;
    p = atomicAdd(&g_cnt[d.x], 1); if (p < CAP) g_slot[d.x * CAP + p] = s.x;
    p = atomicAdd(&g_cnt[d.y], 1); if (p < CAP) g_slot[d.y * CAP + p] = s.y;
    p = atomicAdd(&g_cnt[d.z], 1); if (p < CAP) g_slot[d.z * CAP + p] = s.z;
    p = atomicAdd(&g_cnt[d.w], 1); if (p < CAP) g_slot[d.w * CAP + p] = s.w;
}

__global__ void build_kernel_scalar(const int* __restrict__ ei, int E) {
    int e = blockIdx.x * blockDim.x + threadIdx.x;
    if (e >= E) return;
    int src = ei[e];
    int dst = ei[E + e];
    int pos = atomicAdd(&g_cnt[dst], 1);
    if (pos < CAP) g_slot[dst * CAP + pos] = src;
}

// ---------------------------------------------------------------------------
// K2: FUSED gather + MLP (R13 structure: one tile per block, overlap comes
// from inter-block scheduling skew with 4 blocks/SM).
// Phase A (gather): 16 lanes per node, lane c owns float4 chunk c; each
//   16-lane group assembles 4 node rows directly into the sA tile:
//   sA[r] = (1+eps)*x[node] + sum_{src in list(node)} x[src]
//   Lane 0 self-cleans g_cnt[node] after the warp's broadcast read (program
//   order within the warp makes this safe; each node is owned by exactly one
//   lane-group) -> no separate zeroing kernel.
// Phase B (GEMM): 4x4 micro-tile per thread, out = relu(sA@W1+b1)@W2+b2.
//   H tile reuses sA (sync-guarded). Smem 48KB static, <=64 regs -> 4/SM.
// ---------------------------------------------------------------------------
__global__ void __launch_bounds__(256, 4)
fused_mlp_kernel(const float* __restrict__ x, const float* __restrict__ eps,
                 const float* __restrict__ W1, const float* __restrict__ b1,
                 const float* __restrict__ W2, const float* __restrict__ b2,
                 float* __restrict__ out, int N) {
    __shared__ float sA[BM * D];      // 16 KB: gathered tile, then H tile
    __shared__ float sW1[D * D];      // 16 KB
    __shared__ float sW2[D * D];      // 16 KB

    int tid = threadIdx.x;
    int row_base = blockIdx.x * BM;

    // Stage weights (float4, coalesced) — issued first so they overlap gather
    {
        const float4* w1v = reinterpret_cast<const float4*>(W1);
        const float4* w2v = reinterpret_cast<const float4*>(W2);
        float4* s1v = reinterpret_cast<float4*>(sW1);
        float4* s2v = reinterpret_cast<float4*>(sW2);
        #pragma unroll
        for (int t = 0; t < 4; t++) {      // 1024 float4 / 256 threads
            s1v[tid + t * 256] = w1v[tid + t * 256];
            s2v[tid + t * 256] = w2v[tid + t * 256];
        }
    }

    // ---------------- Phase A: gather tile into sA ----------------
    {
        float s = 1.0f + __ldg(eps);
        int grp = tid >> 4;           // 16 lane-groups
        int c = tid & 15;             // float4 chunk within row
        #pragma unroll
        for (int it = 0; it < 4; it++) {
            int r = grp * 4 + it;     // local row 0..63
            int node = row_base + r;
            float4 acc = make_float4(0.f, 0.f, 0.f, 0.f);
            if (node < N) {
                acc = reinterpret_cast<const float4*>(x + (size_t)node * D)[c];
                acc.x *= s; acc.y *= s; acc.z *= s; acc.w *= s;
                int deg = g_cnt[node];
                if (c == 0) g_cnt[node] = 0;    // self-clean for next launch
                if (deg > CAP) deg = CAP;
                const int* sl = g_slot + (size_t)node * CAP;
                #pragma unroll 4
                for (int p = 0; p < deg; p++) {
                    int src = __ldg(&sl[p]);
                    float4 v = reinterpret_cast<const float4*>(
                                   x + (size_t)src * D)[c];
                    acc.x += v.x; acc.y += v.y; acc.z += v.z; acc.w += v.w;
                }
            }
            *reinterpret_cast<float4*>(&sA[r * D + c * 4]) = acc;
        }
    }
    __syncthreads();

    // ---------------- Phase B: GEMM ----------------
    int tx = tid & 15;                // col group: j0 = tx*4
    int ty = tid >> 4;                // row group: i0 = ty*4
    int j0 = tx * 4;
    int i0 = ty * 4;

    // Layer 1: H = relu(A @ W1 + b1)
    float4 acc[4];
    #pragma unroll
    for (int r = 0; r < 4; r++) acc[r] = make_float4(0.f, 0.f, 0.f, 0.f);

    #pragma unroll
    for (int k0 = 0; k0 < D; k0 += 4) {
        float4 aF[4], bF[4];
        #pragma unroll
        for (int r = 0; r < 4; r++)
            aF[r] = *reinterpret_cast<const float4*>(&sA[(i0 + r) * D + k0]);
        #pragma unroll
        for (int kk = 0; kk < 4; kk++)
            bF[kk] = *reinterpret_cast<const float4*>(&sW1[(k0 + kk) * D + j0]);
        #pragma unroll
        for (int r = 0; r < 4; r++) {
            acc[r].x = fmaf(aF[r].x, bF[0].x, acc[r].x);
            acc[r].y = fmaf(aF[r].x, bF[0].y, acc[r].y);
            acc[r].z = fmaf(aF[r].x, bF[0].z, acc[r].z);
            acc[r].w = fmaf(aF[r].x, bF[0].w, acc[r].w);
            acc[r].x = fmaf(aF[r].y, bF[1].x, acc[r].x);
            acc[r].y = fmaf(aF[r].y, bF[1].y, acc[r].y);
            acc[r].z = fmaf(aF[r].y, bF[1].z, acc[r].z);
            acc[r].w = fmaf(aF[r].y, bF[1].w, acc[r].w);
            acc[r].x = fmaf(aF[r].z, bF[2].x, acc[r].x);
            acc[r].y = fmaf(aF[r].z, bF[2].y, acc[r].y);
            acc[r].z = fmaf(aF[r].z, bF[2].z, acc[r].z);
            acc[r].w = fmaf(aF[r].z, bF[2].w, acc[r].w);
            acc[r].x = fmaf(aF[r].w, bF[3].x, acc[r].x);
            acc[r].y = fmaf(aF[r].w, bF[3].y, acc[r].y);
            acc[r].z = fmaf(aF[r].w, bF[3].z, acc[r].z);
            acc[r].w = fmaf(aF[r].w, bF[3].w, acc[r].w);
        }
    }

    // bias + relu, write H into sA (everyone is done reading A)
    float4 b1v = __ldg(reinterpret_cast<const float4*>(b1 + j0));
    __syncthreads();
    #pragma unroll
    for (int r = 0; r < 4; r++) {
        float4 h;
        h.x = fmaxf(acc[r].x + b1v.x, 0.f);
        h.y = fmaxf(acc[r].y + b1v.y, 0.f);
        h.z = fmaxf(acc[r].z + b1v.z, 0.f);
        h.w = fmaxf(acc[r].w + b1v.w, 0.f);
        *reinterpret_cast<float4*>(&sA[(i0 + r) * D + j0]) = h;
    }
    __syncthreads();

    // Layer 2: out = H @ W2 + b2
    #pragma unroll
    for (int r = 0; r < 4; r++) acc[r] = make_float4(0.f, 0.f, 0.f, 0.f);

    #pragma unroll
    for (int k0 = 0; k0 < D; k0 += 4) {
        float4 aF[4], bF[4];
        #pragma unroll
        for (int r = 0; r < 4; r++)
            aF[r] = *reinterpret_cast<const float4*>(&sA[(i0 + r) * D + k0]);
        #pragma unroll
        for (int kk = 0; kk < 4; kk++)
            bF[kk] = *reinterpret_cast<const float4*>(&sW2[(k0 + kk) * D + j0]);
        #pragma unroll
        for (int r = 0; r < 4; r++) {
            acc[r].x = fmaf(aF[r].x, bF[0].x, acc[r].x);
            acc[r].y = fmaf(aF[r].x, bF[0].y, acc[r].y);
            acc[r].z = fmaf(aF[r].x, bF[0].z, acc[r].z);
            acc[r].w = fmaf(aF[r].x, bF[0].w, acc[r].w);
            acc[r].x = fmaf(aF[r].y, bF[1].x, acc[r].x);
            acc[r].y = fmaf(aF[r].y, bF[1].y, acc[r].y);
            acc[r].z = fmaf(aF[r].y, bF[1].z, acc[r].z);
            acc[r].w = fmaf(aF[r].y, bF[1].w, acc[r].w);
            acc[r].x = fmaf(aF[r].z, bF[2].x, acc[r].x);
            acc[r].y = fmaf(aF[r].z, bF[2].y, acc[r].y);
            acc[r].z = fmaf(aF[r].z, bF[2].z, acc[r].z);
            acc[r].w = fmaf(aF[r].z, bF[2].w, acc[r].w);
            acc[r].x = fmaf(aF[r].w, bF[3].x, acc[r].x);
            acc[r].y = fmaf(aF[r].w, bF[3].y, acc[r].y);
            acc[r].z = fmaf(aF[r].w, bF[3].z, acc[r].z);
            acc[r].w = fmaf(aF[r].w, bF[3].w, acc[r].w);
        }
    }

    float4 b2v = __ldg(reinterpret_cast<const float4*>(b2 + j0));
    #pragma unroll
    for (int r = 0; r < 4; r++) {
        int grow = row_base + i0 + r;
        if (grow < N) {
            float4 o;
            o.x = acc[r].x + b2v.x;
            o.y = acc[r].y + b2v.y;
            o.z = acc[r].z + b2v.z;
            o.w = acc[r].w + b2v.w;
            *reinterpret_cast<float4*>(out + (size_t)grow * D + j0) = o;
        }
    }
}

// ---------------------------------------------------------------------------
// Launch: build -> fused gather+MLP (single stream, graph-capturable).
// No zeroing kernel: g_cnt is zero-init at load and self-cleaned per launch.
// Input order per metadata: x, edge_index, W1, b1, W2, b2, eps
// ---------------------------------------------------------------------------
extern "C" void kernel_launch(void* const* d_in, const int* in_sizes, int n_in,
                              void* d_out, int out_size) {
    const float* x   = (const float*)d_in[0];
    const int*   ei  = (const int*)d_in[1];     // int32 (JAX x64 disabled)
    const float* W1  = (const float*)d_in[2];
    const float* b1  = (const float*)d_in[3];
    const float* W2  = (const float*)d_in[4];
    const float* b2  = (const float*)d_in[5];
    const float* eps = (const float*)d_in[6];
    float*       out = (float*)d_out;

    int N = in_sizes[0] / D;       // 100000
    int E = in_sizes[1] / 2;       // 1600000

    // K1: build per-dst edge lists (vectorized when E % 4 == 0)
    if ((E & 3) == 0) {
        int E4 = E >> 2;
        build_kernel_v4<<<(E4 + 255) / 256, 256>>>(ei, E4, E);
    } else {
        build_kernel_scalar<<<(E + 255) / 256, 256>>>(ei, E);
    }

    // K2: fused gather + MLP (64-node tiles, 4 blocks/SM)
    fused_mlp_kernel<<<(N + BM - 1) / BM, 256>>>(x, eps, W1, b1, W2, b2,
                                                 out, N);
}

// round 16
// speedup vs baseline: 1.5910x; 1.5910x over previous
#include <cuda_runtime.h>
#include <cuda_bf16.h>

// Problem constants (from reference: N=100000, E=1600000, D=64)
#define MAX_N 100000
#define D 64
#define CAP 64   // per-node edge-list capacity; deg ~ Poisson(16), P(>64) ~ 1e-20
#define BM 64

// Scratch (__device__ globals; no allocs allowed).
// g_cnt is zero-initialized at module load; the fused kernel resets the
// counters it consumed (in a dedicated store burst AFTER the gather reads),
// so every launch starts with all counters at 0.
__device__ int g_slot[MAX_N * CAP];                     // 25.6 MB
__device__ int g_cnt[MAX_N];                            // 400 KB

// ---------------------------------------------------------------------------
// K1: build per-dst edge lists. 4 edges per thread (int4 loads -> 4
// independent atomic->store chains).
// edge_index is int32: [0..E) = src, [E..2E) = dst.
// ---------------------------------------------------------------------------
__global__ void build_kernel_v4(const int* __restrict__ ei, int E4, int E) {
    int i = blockIdx.x * blockDim.x + threadIdx.x;
    if (i >= E4) return;
    int4 s = __ldg(reinterpret_cast<const int4*>(ei) + i);
    int4 d = __ldg(reinterpret_cast<const int4*>(ei + E) + i);
    int p;
    p = atomicAdd(&g_cnt[d.x], 1); if (p < CAP) g_slot[d.x * CAP + p] = s.x;
    p = atomicAdd(&g_cnt[d.y], 1); if (p < CAP) g_slot[d.y * CAP + p] = s.y;
    p = atomicAdd(&g_cnt[d.z], 1); if (p < CAP) g_slot[d.z * CAP + p] = s.z;
    p = atomicAdd(&g_cnt[d.w], 1); if (p < CAP) g_slot[d.w * CAP + p] = s.w;
}

__global__ void build_kernel_scalar(const int* __restrict__ ei, int E) {
    int e = blockIdx.x * blockDim.x + threadIdx.x;
    if (e >= E) return;
    int src = ei[e];
    int dst = ei[E + e];
    int pos = atomicAdd(&g_cnt[dst], 1);
    if (pos < CAP) g_slot[dst * CAP + pos] = src;
}

// ---------------------------------------------------------------------------
// K2: FUSED gather + MLP (R13 structure; one 64-node tile per block,
// overlap across the 4 co-resident blocks via scheduling skew).
// Phase A (gather): 16 lanes per node, lane c owns float4 chunk c:
//   sA[r] = (1+eps)*x[node] + sum_{src in list(node)} x[src]
//   NO STORES inside the gather loop -- keeps the dependent-load chain
//   freely pipelinable (the R14/R15 in-loop counter store serialized it).
// Counter clean: after S1, threads 0..63 reset this block's 64 counters
//   (all deg reads completed before the barrier; stores sit outside any
//   load loop).
// Phase B (GEMM): 4x4 micro-tile per thread, out = relu(sA@W1+b1)@W2+b2.
//   H tile reuses sA (sync-guarded). Smem 48KB static, <=64 regs -> 4/SM.
// ---------------------------------------------------------------------------
__global__ void __launch_bounds__(256, 4)
fused_mlp_kernel(const float* __restrict__ x, const float* __restrict__ eps,
                 const float* __restrict__ W1, const float* __restrict__ b1,
                 const float* __restrict__ W2, const float* __restrict__ b2,
                 float* __restrict__ out, int N) {
    __shared__ float sA[BM * D];      // 16 KB: gathered tile, then H tile
    __shared__ float sW1[D * D];      // 16 KB
    __shared__ float sW2[D * D];      // 16 KB

    int tid = threadIdx.x;
    int row_base = blockIdx.x * BM;

    // Stage weights (float4, coalesced) — issued first so they overlap gather
    {
        const float4* w1v = reinterpret_cast<const float4*>(W1);
        const float4* w2v = reinterpret_cast<const float4*>(W2);
        float4* s1v = reinterpret_cast<float4*>(sW1);
        float4* s2v = reinterpret_cast<float4*>(sW2);
        #pragma unroll
        for (int t = 0; t < 4; t++) {      // 1024 float4 / 256 threads
            s1v[tid + t * 256] = w1v[tid + t * 256];
            s2v[tid + t * 256] = w2v[tid + t * 256];
        }
    }

    // ---------------- Phase A: gather tile into sA (no stores in loop) ----
    {
        float s = 1.0f + __ldg(eps);
        int grp = tid >> 4;           // 16 lane-groups
        int c = tid & 15;             // float4 chunk within row
        #pragma unroll
        for (int it = 0; it < 4; it++) {
            int r = grp * 4 + it;     // local row 0..63
            int node = row_base + r;
            float4 acc = make_float4(0.f, 0.f, 0.f, 0.f);
            if (node < N) {
                acc = reinterpret_cast<const float4*>(x + (size_t)node * D)[c];
                acc.x *= s; acc.y *= s; acc.z *= s; acc.w *= s;
                int deg = __ldg(&g_cnt[node]);
                if (deg > CAP) deg = CAP;
                const int* sl = g_slot + (size_t)node * CAP;
                #pragma unroll 4
                for (int p = 0; p < deg; p++) {
                    int src = __ldg(&sl[p]);
                    float4 v = reinterpret_cast<const float4*>(
                                   x + (size_t)src * D)[c];
                    acc.x += v.x; acc.y += v.y; acc.z += v.z; acc.w += v.w;
                }
            }
            *reinterpret_cast<float4*>(&sA[r * D + c * 4]) = acc;
        }
    }
    __syncthreads();                  // S1: tile complete, all deg reads done

    // Counter clean for next launch (dedicated burst, outside load loops)
    if (tid < BM) {
        int node = row_base + tid;
        if (node < N) g_cnt[node] = 0;
    }

    // ---------------- Phase B: GEMM ----------------
    int tx = tid & 15;                // col group: j0 = tx*4
    int ty = tid >> 4;                // row group: i0 = ty*4
    int j0 = tx * 4;
    int i0 = ty * 4;

    // Layer 1: H = relu(A @ W1 + b1)
    float4 acc[4];
    #pragma unroll
    for (int r = 0; r < 4; r++) acc[r] = make_float4(0.f, 0.f, 0.f, 0.f);

    #pragma unroll
    for (int k0 = 0; k0 < D; k0 += 4) {
        float4 aF[4], bF[4];
        #pragma unroll
        for (int r = 0; r < 4; r++)
            aF[r] = *reinterpret_cast<const float4*>(&sA[(i0 + r) * D + k0]);
        #pragma unroll
        for (int kk = 0; kk < 4; kk++)
            bF[kk] = *reinterpret_cast<const float4*>(&sW1[(k0 + kk) * D + j0]);
        #pragma unroll
        for (int r = 0; r < 4; r++) {
            acc[r].x = fmaf(aF[r].x, bF[0].x, acc[r].x);
            acc[r].y = fmaf(aF[r].x, bF[0].y, acc[r].y);
            acc[r].z = fmaf(aF[r].x, bF[0].z, acc[r].z);
            acc[r].w = fmaf(aF[r].x, bF[0].w, acc[r].w);
            acc[r].x = fmaf(aF[r].y, bF[1].x, acc[r].x);
            acc[r].y = fmaf(aF[r].y, bF[1].y, acc[r].y);
            acc[r].z = fmaf(aF[r].y, bF[1].z, acc[r].z);
            acc[r].w = fmaf(aF[r].y, bF[1].w, acc[r].w);
            acc[r].x = fmaf(aF[r].z, bF[2].x, acc[r].x);
            acc[r].y = fmaf(aF[r].z, bF[2].y, acc[r].y);
            acc[r].z = fmaf(aF[r].z, bF[2].z, acc[r].z);
            acc[r].w = fmaf(aF[r].z, bF[2].w, acc[r].w);
            acc[r].x = fmaf(aF[r].w, bF[3].x, acc[r].x);
            acc[r].y = fmaf(aF[r].w, bF[3].y, acc[r].y);
            acc[r].z = fmaf(aF[r].w, bF[3].z, acc[r].z);
            acc[r].w = fmaf(aF[r].w, bF[3].w, acc[r].w);
        }
    }

    // bias + relu, write H into sA (everyone is done reading A)
    float4 b1v = __ldg(reinterpret_cast<const float4*>(b1 + j0));
    __syncthreads();
    #pragma unroll
    for (int r = 0; r < 4; r++) {
        float4 h;
        h.x = fmaxf(acc[r].x + b1v.x, 0.f);
        h.y = fmaxf(acc[r].y + b1v.y, 0.f);
        h.z = fmaxf(acc[r].z + b1v.z, 0.f);
        h.w = fmaxf(acc[r].w + b1v.w, 0.f);
        *reinterpret_cast<float4*>(&sA[(i0 + r) * D + j0]) = h;
    }
    __syncthreads();

    // Layer 2: out = H @ W2 + b2
    #pragma unroll
    for (int r = 0; r < 4; r++) acc[r] = make_float4(0.f, 0.f, 0.f, 0.f);

    #pragma unroll
    for (int k0 = 0; k0 < D; k0 += 4) {
        float4 aF[4], bF[4];
        #pragma unroll
        for (int r = 0; r < 4; r++)
            aF[r] = *reinterpret_cast<const float4*>(&sA[(i0 + r) * D + k0]);
        #pragma unroll
        for (int kk = 0; kk < 4; kk++)
            bF[kk] = *reinterpret_cast<const float4*>(&sW2[(k0 + kk) * D + j0]);
        #pragma unroll
        for (int r = 0; r < 4; r++) {
            acc[r].x = fmaf(aF[r].x, bF[0].x, acc[r].x);
            acc[r].y = fmaf(aF[r].x, bF[0].y, acc[r].y);
            acc[r].z = fmaf(aF[r].x, bF[0].z, acc[r].z);
            acc[r].w = fmaf(aF[r].x, bF[0].w, acc[r].w);
            acc[r].x = fmaf(aF[r].y, bF[1].x, acc[r].x);
            acc[r].y = fmaf(aF[r].y, bF[1].y, acc[r].y);
            acc[r].z = fmaf(aF[r].y, bF[1].z, acc[r].z);
            acc[r].w = fmaf(aF[r].y, bF[1].w, acc[r].w);
            acc[r].x = fmaf(aF[r].z, bF[2].x, acc[r].x);
            acc[r].y = fmaf(aF[r].z, bF[2].y, acc[r].y);
            acc[r].z = fmaf(aF[r].z, bF[2].z, acc[r].z);
            acc[r].w = fmaf(aF[r].z, bF[2].w, acc[r].w);
            acc[r].x = fmaf(aF[r].w, bF[3].x, acc[r].x);
            acc[r].y = fmaf(aF[r].w, bF[3].y, acc[r].y);
            acc[r].z = fmaf(aF[r].w, bF[3].z, acc[r].z);
            acc[r].w = fmaf(aF[r].w, bF[3].w, acc[r].w);
        }
    }

    float4 b2v = __ldg(reinterpret_cast<const float4*>(b2 + j0));
    #pragma unroll
    for (int r = 0; r < 4; r++) {
        int grow = row_base + i0 + r;
        if (grow < N) {
            float4 o;
            o.x = acc[r].x + b2v.x;
            o.y = acc[r].y + b2v.y;
            o.z = acc[r].z + b2v.z;
            o.w = acc[r].w + b2v.w;
            *reinterpret_cast<float4*>(out + (size_t)grow * D + j0) = o;
        }
    }
}

// ---------------------------------------------------------------------------
// Launch: build -> fused gather+MLP (single stream, graph-capturable).
// No zeroing kernel: g_cnt zero-init at load + post-read clean per launch.
// Input order per metadata: x, edge_index, W1, b1, W2, b2, eps
// ---------------------------------------------------------------------------
extern "C" void kernel_launch(void* const* d_in, const int* in_sizes, int n_in,
                              void* d_out, int out_size) {
    const float* x   = (const float*)d_in[0];
    const int*   ei  = (const int*)d_in[1];     // int32 (JAX x64 disabled)
    const float* W1  = (const float*)d_in[2];
    const float* b1  = (const float*)d_in[3];
    const float* W2  = (const float*)d_in[4];
    const float* b2  = (const float*)d_in[5];
    const float* eps = (const float*)d_in[6];
    float*       out = (float*)d_out;

    int N = in_sizes[0] / D;       // 100000
    int E = in_sizes[1] / 2;       // 1600000

    // K1: build per-dst edge lists (vectorized when E % 4 == 0)
    if ((E & 3) == 0) {
        int E4 = E >> 2;
        build_kernel_v4<<<(E4 + 255) / 256, 256>>>(ei, E4, E);
    } else {
        build_kernel_scalar<<<(E + 255) / 256, 256>>>(ei, E);
    }

    // K2: fused gather + MLP (64-node tiles, 4 blocks/SM)
    fused_mlp_kernel<<<(N + BM - 1) / BM, 256>>>(x, eps, W1, b1, W2, b2,
                                                 out, N);
}